// round 8
// baseline (speedup 1.0000x reference)
#include <cuda_runtime.h>
#include <cuda_fp16.h>
#include <math.h>

#define NB   4
#define CH   16
#define HWSZ 65536
#define EPSV 1e-6f
#define LOG2E_T 14.4269504089f     // (1/TEMP) * log2(e)
#define LN2F    0.69314718056f

typedef unsigned long long u64;
typedef unsigned int u32;

// Channels-last normalized features in fp16: [n][pix][16 halves] = 8 MB
__device__ u32 g_fnh[(size_t)NB * HWSZ * 8];
__device__ float g_lp[512];
__device__ float g_dp[1024];
__device__ unsigned int g_ctr = 0;

// ---------------- helpers ----------------
__device__ __forceinline__ u64 f2add(u64 a, u64 b) {
    u64 d; asm("add.rn.f32x2 %0,%1,%2;" : "=l"(d) : "l"(a), "l"(b)); return d;
}
__device__ __forceinline__ u64 pack2(float lo, float hi) {
    u64 d; asm("mov.b64 %0,{%1,%2};" : "=l"(d) : "f"(lo), "f"(hi)); return d;
}
__device__ __forceinline__ void unpack2(u64 v, float& lo, float& hi) {
    asm("mov.b64 {%0,%1},%2;" : "=f"(lo), "=f"(hi) : "l"(v));
}
__device__ __forceinline__ float ex2f(float x) {
    float r; asm("ex2.approx.ftz.f32 %0,%1;" : "=f"(r) : "f"(x)); return r;
}
// fp16 (half2) 16-dim dot: 8 HFMA2 in 2 chains, join, fold, 1 convert
__device__ __forceinline__ float dot16h(const u32 a[8], const u32 b[8]) {
    u32 p, q, r, rs, r2;
    asm("mul.rn.f16x2 %0,%1,%2;" : "=r"(p) : "r"(a[0]), "r"(b[0]));
    asm("mul.rn.f16x2 %0,%1,%2;" : "=r"(q) : "r"(a[1]), "r"(b[1]));
    asm("fma.rn.f16x2 %0,%1,%2,%3;" : "=r"(p) : "r"(a[2]), "r"(b[2]), "r"(p));
    asm("fma.rn.f16x2 %0,%1,%2,%3;" : "=r"(q) : "r"(a[3]), "r"(b[3]), "r"(q));
    asm("fma.rn.f16x2 %0,%1,%2,%3;" : "=r"(p) : "r"(a[4]), "r"(b[4]), "r"(p));
    asm("fma.rn.f16x2 %0,%1,%2,%3;" : "=r"(q) : "r"(a[5]), "r"(b[5]), "r"(q));
    asm("fma.rn.f16x2 %0,%1,%2,%3;" : "=r"(p) : "r"(a[6]), "r"(b[6]), "r"(p));
    asm("fma.rn.f16x2 %0,%1,%2,%3;" : "=r"(q) : "r"(a[7]), "r"(b[7]), "r"(q));
    asm("add.rn.f16x2 %0,%1,%2;" : "=r"(r) : "r"(p), "r"(q));
    asm("prmt.b32 %0,%1,%1,0x1032;" : "=r"(rs) : "r"(r));
    asm("add.rn.f16x2 %0,%1,%2;" : "=r"(r2) : "r"(r), "r"(rs));
    float f;
    asm("{.reg .b16 lo,hi; mov.b32 {lo,hi}, %1; cvt.f32.f16 %0, lo;}"
        : "=f"(f) : "r"(r2));
    return f;
}
// scale 8 half2 regs by splat constant (fp16)
__device__ __forceinline__ void scale16h(u32 h[8], u32 k2) {
#pragma unroll
    for (int i = 0; i < 8; i++)
        asm("mul.rn.f16x2 %0,%1,%2;" : "=r"(h[i]) : "r"(h[i]), "r"(k2));
}
// load 16 halves (as 8 u32) from a parity sub-array with XOR swizzle
__device__ __forceinline__ void load16h(const char* base, int idx, u32 h[8]) {
    int sw = ((idx >> 2) & 1) << 4;
    const char* p = base + (idx << 5);
    uint4 a = *(const uint4*)(p + sw);
    uint4 b = *(const uint4*)(p + (16 ^ sw));
    h[0]=a.x; h[1]=a.y; h[2]=a.z; h[3]=a.w;
    h[4]=b.x; h[5]=b.y; h[6]=b.z; h[7]=b.w;
}

// ---------------------------------------------------------------------------
// Kernel 1: L2-normalize + transpose + fp16 quantize. 1 pixel/thread
// (best-measured shape: grid 1024 x 256).
// ---------------------------------------------------------------------------
__global__ void __launch_bounds__(256)
k_norm(const float* __restrict__ f) {
    int idx = blockIdx.x * 256 + threadIdx.x;  // 0 .. N*HW-1
    int n   = idx >> 16;
    int pix = idx & 65535;
    const float* b = f + (size_t)n * CH * HWSZ + pix;
    float v[CH];
    float ss = 0.f;
#pragma unroll
    for (int c = 0; c < CH; c++) {
        v[c] = b[(size_t)c * HWSZ];
        ss = fmaf(v[c], v[c], ss);
    }
    float inv = 1.0f / fmaxf(sqrtf(ss), 1e-12f);
    u32 h[8];
#pragma unroll
    for (int c2 = 0; c2 < 8; c2++) {
        __half2 hh = __floats2half2_rn(v[c2*2] * inv, v[c2*2+1] * inv);
        h[c2] = *(u32*)&hh;
    }
    uint4* o = (uint4*)(g_fnh + (size_t)idx * 8);
    o[0] = make_uint4(h[0], h[1], h[2], h[3]);
    o[1] = make_uint4(h[4], h[5], h[6], h[7]);
}

// ---------------------------------------------------------------------------
// Kernel 2: local 11x11 term. Block = (n, 8 center rows, 64-col quarter).
// 128 threads; thread (rp, cp) owns 2x2 quad rows i0+2rp, i0+2rp+1, cols
// 64*hq + 2cp, +1. Halo = 18 rows x 80 cols, fp16 channels-last, even/odd
// parity split + XOR swizzle. 51.8 KB smem -> 4 blocks/SM, single wave.
// ---------------------------------------------------------------------------
#define ROWB 2560                    // bytes per row slot (40+40 vecs of 32B)
__global__ void __launch_bounds__(128, 4)
k_local(const int* __restrict__ labels) {
    extern __shared__ char sm[];
    char* sF   = sm;                      // 18 * 2560 = 46080 B
    int*  sLab = (int*)(sm + 18 * ROWB);  // 18 * 80 ints = 5760 B

    const int bx  = blockIdx.x;           // 0..511
    const int n   = bx >> 7;
    const int rem = bx & 127;
    const int i0  = (rem >> 2) << 3;      // first center row (mult of 8)
    const int hq  = rem & 3;              // which 64-col quarter
    const int cb  = hq * 64 - 8;          // tile base col (global)
    const int t   = threadIdx.x;

    // ---- fill halo: 18 rows x 80 cols ----
    {
        const uint4* src = (const uint4*)(g_fnh + (size_t)n * HWSZ * 8);
#pragma unroll
        for (int k = 0; k < 23; k++) {
            int lin = t + (k << 7);           // need 2880
            if (lin < 2880) {
                int rr = lin / 160;
                int w  = lin - rr * 160;
                int ch = w & 1;
                int x  = w >> 1;              // tile col 0..79
                int row = i0 - 5 + rr;
                int g   = cb + x;
                if ((unsigned)row < 256u && (unsigned)g < 256u) {
                    uint4 v = src[(size_t)((row << 8) + g) * 2 + ch];
                    int parity = x & 1, e = x >> 1;
                    *(uint4*)(sF + rr * ROWB + parity * 1280 + (e << 5)
                              + ((ch ^ ((e >> 2) & 1)) << 4)) = v;
                }
            }
        }
        const int* ls = labels + n * HWSZ;
#pragma unroll
        for (int k = 0; k < 12; k++) {
            int lin = t + (k << 7);           // need 1440
            if (lin < 1440) {
                int rr = lin / 80;
                int x  = lin - rr * 80;
                int row = i0 - 5 + rr;
                int g   = cb + x;
                bool ok = ((unsigned)row < 256u) && ((unsigned)g < 256u);
                sLab[rr * 80 + (x & 1) * 40 + (x >> 1)] =
                    ok ? ls[(row << 8) + g] : (int)0x80000000;
            }
        }
    }
    __syncthreads();

    const int rp = t >> 5;               // 0..3 (warp-uniform)
    const int cp = t & 31;
    const int tc = cp + 4;
    const int sA = 2 * rp + 5;
    const int sB = sA + 1;

    u32 cvAe[8], cvAo[8], cvBe[8], cvBo[8];
    load16h(sF + sA * ROWB,        tc, cvAe);
    load16h(sF + sA * ROWB + 1280, tc, cvAo);
    load16h(sF + sB * ROWB,        tc, cvBe);
    load16h(sF + sB * ROWB + 1280, tc, cvBo);
    __half2 kt = __floats2half2_rn(LOG2E_T, LOG2E_T);
    u32 kt2 = *(u32*)&kt;
    scale16h(cvAe, kt2); scale16h(cvAo, kt2);
    scale16h(cvBe, kt2); scale16h(cvBo, kt2);
    const int clAe = sLab[sA * 80 + tc];
    const int clAo = sLab[sA * 80 + 40 + tc];
    const int clBe = sLab[sB * 80 + tc];
    const int clBo = sLab[sB * 80 + 40 + tc];

    u64 SDAe = 0, SDAo = 0, SDBe = 0, SDBo = 0;   // packed {S, D}
    int MAe = 0, MAo = 0, MBe = 0, MBo = 0;

#pragma unroll 1
    for (int v = 0; v < 12; v++) {
        int s   = 2 * rp + v;
        int row = i0 - 5 + s;
        if ((unsigned)row >= 256u) continue;   // warp-uniform
        const bool rokA = (v <= 10);
        const bool rokB = (v >= 1);
        const char* rowE = sF + s * ROWB;
        const char* rowO = rowE + 1280;
        const int* labE = sLab + s * 80;
        const int* labO = labE + 40;

        // even-pixel neighbors
#pragma unroll
        for (int u = 0; u < 6; u++) {
            int e  = cp + 2 + u;
            int gx = cb + (e << 1);
            bool vld = (unsigned)gx < 256u;
            u32 nv[8]; load16h(rowE, e, nv);
            int lb = labE[e];
            {
                float dAo = dot16h(cvAo, nv);      // already log2-scaled
                float dBo = dot16h(cvBo, nv);
                float eA = ex2f(dAo), eB = ex2f(dBo);
                if (vld && rokA && lb == clAo) { SDAo = f2add(SDAo, pack2(eA, dAo)); MAo++; }
                if (vld && rokB && lb == clBo) { SDBo = f2add(SDBo, pack2(eB, dBo)); MBo++; }
            }
            if (u != 5) {
                float dAe = dot16h(cvAe, nv);
                float dBe = dot16h(cvBe, nv);
                float eA = ex2f(dAe), eB = ex2f(dBe);
                if (vld && rokA && lb == clAe) { SDAe = f2add(SDAe, pack2(eA, dAe)); MAe++; }
                if (vld && rokB && lb == clBe) { SDBe = f2add(SDBe, pack2(eB, dBe)); MBe++; }
            }
        }
        // odd-pixel neighbors
#pragma unroll
        for (int u = 0; u < 6; u++) {
            int o  = cp + 1 + u;
            int gx = cb + (o << 1) + 1;
            bool vld = (unsigned)gx < 256u;
            u32 nv[8]; load16h(rowO, o, nv);
            int lb = labO[o];
            {
                float dAe = dot16h(cvAe, nv);
                float dBe = dot16h(cvBe, nv);
                float eA = ex2f(dAe), eB = ex2f(dBe);
                if (vld && rokA && lb == clAe) { SDAe = f2add(SDAe, pack2(eA, dAe)); MAe++; }
                if (vld && rokB && lb == clBe) { SDBe = f2add(SDBe, pack2(eB, dBe)); MBe++; }
            }
            if (u != 0) {
                float dAo = dot16h(cvAo, nv);
                float dBo = dot16h(cvBo, nv);
                float eA = ex2f(dAo), eB = ex2f(dBo);
                if (vld && rokA && lb == clAo) { SDAo = f2add(SDAo, pack2(eA, dAo)); MAo++; }
                if (vld && rokB && lb == clBo) { SDBo = f2add(SDBo, pack2(eB, dBo)); MBo++; }
            }
        }
    }

    float SAe, DAe, SAo, DAo, SBe, DBe, SBo, DBo;
    unpack2(SDAe, SAe, DAe);  unpack2(SDAo, SAo, DAo);
    unpack2(SDBe, SBe, DBe);  unpack2(SDBo, SBo, DBo);

    float cAe = fmaf((float)MAe, __logf(SAe + EPSV), -LN2F * DAe);
    float cAo = fmaf((float)MAo, __logf(SAo + EPSV), -LN2F * DAo);
    float cBe = fmaf((float)MBe, __logf(SBe + EPSV), -LN2F * DBe);
    float cBo = fmaf((float)MBo, __logf(SBo + EPSV), -LN2F * DBo);
    int ciA = i0 + 2 * rp, ciB = ciA + 1;
    int j0  = hq * 64 + 2 * cp, j1 = j0 + 1;
    float chA = (float)(11 - max(0, 5 - ciA) - max(0, ciA - 250));
    float chB = (float)(11 - max(0, 5 - ciB) - max(0, ciB - 250));
    float cw0 = (float)(11 - max(0, 5 - j0)  - max(0, j0  - 250));
    float cw1 = (float)(11 - max(0, 5 - j1)  - max(0, j1  - 250));
    float val = (cAe / (chA * cw0) + cAo / (chA * cw1)
               + cBe / (chB * cw0) + cBo / (chB * cw1)) * (1.0f / (4.0f * 65536.0f));

    __shared__ float wred[4];
#pragma unroll
    for (int o = 16; o > 0; o >>= 1) val += __shfl_down_sync(0xffffffffu, val, o);
    if ((t & 31) == 0) wred[t >> 5] = val;
    __syncthreads();
    if (t == 0) g_lp[bx] = (wred[0] + wred[1]) + (wred[2] + wred[3]);
}

// ---------------------------------------------------------------------------
// Kernel 3: directional term, one n per 256-block slice (grid 1024) + final
// folded reduction in the last-finishing block.
// ---------------------------------------------------------------------------
__global__ void __launch_bounds__(256)
k_dir(const int* __restrict__ labels, const int* __restrict__ dirs,
      float* __restrict__ out) {
    const int bx = blockIdx.x;                  // 0..1023
    const int t  = threadIdx.x;
    const int nn  = bx >> 8;                    // batch of the features
    const int pix = ((bx & 255) << 8) + t;      // pixel index i*256+j
    const int i = pix >> 8, j = pix & 255;

    int off[NB], lc[NB];
#pragma unroll
    for (int k = 0; k < NB; k++) {
        int dik = dirs[(k * 2 + 0) * HWSZ + pix];
        int djk = dirs[(k * 2 + 1) * HWSZ + pix];
        off[k] = ((i + dik) << 8) + (j + djk);
        lc[k]  = labels[k * HWSZ + pix];
    }

    const uint4* base = (const uint4*)(g_fnh + (size_t)nn * HWSZ * 8);
    u32 cv[8];
    {
        uint4 a = base[(size_t)pix * 2], b = base[(size_t)pix * 2 + 1];
        cv[0]=a.x; cv[1]=a.y; cv[2]=a.z; cv[3]=a.w;
        cv[4]=b.x; cv[5]=b.y; cv[6]=b.z; cv[7]=b.w;
    }
    __half2 kt = __floats2half2_rn(LOG2E_T, LOG2E_T);
    scale16h(cv, *(u32*)&kt);

    float dt[NB]; bool mk[NB]; float S = 0.f;
#pragma unroll
    for (int k = 0; k < NB; k++) {
        u32 nv[8];
        uint4 a = base[(size_t)off[k] * 2], b = base[(size_t)off[k] * 2 + 1];
        nv[0]=a.x; nv[1]=a.y; nv[2]=a.z; nv[3]=a.w;
        nv[4]=b.x; nv[5]=b.y; nv[6]=b.z; nv[7]=b.w;
        dt[k] = dot16h(cv, nv);                 // log2-scaled logit
        mk[k] = (labels[nn * HWSZ + off[k]] == lc[k]);
        S += mk[k] ? ex2f(dt[k]) : 0.f;
    }
    float logS = __logf(S + EPSV);
    float sum = 0.f;
#pragma unroll
    for (int k = 0; k < NB; k++)
        sum += mk[k] ? (logS - LN2F * dt[k]) : __int_as_float(0x7f800000);
    float val = sum * (1.0f / (16.0f * 65536.0f));

    // block reduce (deterministic), last-finishing block folds the final sum
    __shared__ float wred[8];
    __shared__ bool  slast;
#pragma unroll
    for (int o = 16; o > 0; o >>= 1) val += __shfl_down_sync(0xffffffffu, val, o);
    if ((t & 31) == 0) wred[t >> 5] = val;
    __syncthreads();
    if (t < 32) {
        float x = (t < 8) ? wred[t] : 0.f;
#pragma unroll
        for (int o = 4; o > 0; o >>= 1) x += __shfl_down_sync(0xffffffffu, x, o);
        if (t == 0) {
            g_dp[bx] = x;
            __threadfence();
            unsigned old = atomicAdd(&g_ctr, 1u);
            slast = (old == 1023u);
        }
    }
    __syncthreads();

    if (slast) {
        float v = g_lp[t] + g_lp[t + 256]
                + g_dp[t] + g_dp[t + 256] + g_dp[t + 512] + g_dp[t + 768];
#pragma unroll
        for (int o = 16; o > 0; o >>= 1) v += __shfl_down_sync(0xffffffffu, v, o);
        if ((t & 31) == 0) wred[t >> 5] = v;
        __syncthreads();
        if (t == 0) {
            float s = 0.f;
#pragma unroll
            for (int w = 0; w < 8; w++) s += wred[w];
            out[0] = s;
            g_ctr = 0;   // reset for next graph replay
        }
    }
}

// ---------------------------------------------------------------------------
extern "C" void kernel_launch(void* const* d_in, const int* in_sizes, int n_in,
                              void* d_out, int out_size) {
    const float* feat   = (const float*)d_in[0];
    const int*   labels = (const int*)d_in[1];
    const int*   dirs   = (const int*)d_in[2];
    float* out = (float*)d_out;

    const int smem = 18 * ROWB + 18 * 80 * 4;   // 46080 + 5760 = 51840 B
    cudaFuncSetAttribute(k_local, cudaFuncAttributeMaxDynamicSharedMemorySize, smem);

    k_norm<<<1024, 256>>>(feat);
    k_local<<<512, 128, smem>>>(labels);
    k_dir<<<1024, 256>>>(labels, dirs, out);
}